// round 5
// baseline (speedup 1.0000x reference)
#include <cuda_runtime.h>

#define N_GRID 64
#define N1 65
#define B_PTS 262144
#define W_FEAT 256
#define NBINS 262144                       // 64^3 Morton bins (exact)
#define SCAN_BLOCK 256
#define SCAN_ITEMS 8
#define CHUNK (SCAN_BLOCK * SCAN_ITEMS)    // 2048
#define NB_SCAN (NBINS / CHUNK)            // 128
#define MAIN_BLOCK 1024

// Scratch (device globals: allocation-free per harness rules)
__device__ int    g_hist[NBINS];
__device__ int    g_off[NBINS];
__device__ int    g_bsum[NB_SCAN];
__device__ int    g_cellid[B_PTS];
__device__ float4 g_sorted[B_PTS];         // (px,py,pz, bitcast(pt))

// Expand 6 low bits of v so they occupy every 3rd bit (Morton helper)
__device__ __forceinline__ unsigned expand3(unsigned v) {
    v &= 0x3FFu;
    v = (v | (v << 16)) & 0x030000FFu;
    v = (v | (v << 8))  & 0x0300F00Fu;
    v = (v | (v << 4))  & 0x030C30C3u;
    v = (v | (v << 2))  & 0x09249249u;
    return v;
}

// ---------------------------------------------------------------------------
// K0: zero histogram (every call, for graph-replay determinism)
__global__ void k_zero_hist() {
    int i = blockIdx.x * blockDim.x + threadIdx.x;
    if (i < NBINS) g_hist[i] = 0;
}

// K1: Morton cell id per point + histogram
__global__ void k_cells(const float* __restrict__ x) {
    int pt = blockIdx.x * blockDim.x + threadIdx.x;
    if (pt >= B_PTS) return;
    float rx = (x[3 * pt + 0] + 1.0f) * 32.0f;
    float ry = (x[3 * pt + 1] + 1.0f) * 32.0f;
    float rz = (x[3 * pt + 2] + 1.0f) * 32.0f;
    int ix = min(max((int)floorf(rx), 0), N_GRID - 1);
    int iy = min(max((int)floorf(ry), 0), N_GRID - 1);
    int iz = min(max((int)floorf(rz), 0), N_GRID - 1);
    unsigned code = expand3((unsigned)ix) | (expand3((unsigned)iy) << 1)
                  | (expand3((unsigned)iz) << 2);          // 18-bit Morton
    g_cellid[pt] = (int)code;
    atomicAdd(&g_hist[code], 1);
}

// K2a: per-chunk reduction -> g_bsum[b]
__global__ void k_reduce() {
    int b = blockIdx.x, tid = threadIdx.x;
    int s = 0;
#pragma unroll
    for (int i = 0; i < SCAN_ITEMS; i++)
        s += g_hist[b * CHUNK + tid * SCAN_ITEMS + i];
#pragma unroll
    for (int d = 16; d > 0; d >>= 1) s += __shfl_down_sync(0xffffffffu, s, d);
    __shared__ int wsum[SCAN_BLOCK / 32];
    int lane = tid & 31, wid = tid >> 5;
    if (lane == 0) wsum[wid] = s;
    __syncthreads();
    if (wid == 0) {
        s = (lane < SCAN_BLOCK / 32) ? wsum[lane] : 0;
#pragma unroll
        for (int d = 16; d > 0; d >>= 1) s += __shfl_down_sync(0xffffffffu, s, d);
        if (lane == 0) g_bsum[b] = s;
    }
}

// K2b: per-chunk exclusive scan; each block derives its own prefix of g_bsum
// inline (128 entries -> one warp-level reduce), eliminating a separate launch.
__global__ void k_scan_chunks() {
    int b = blockIdx.x, tid = threadIdx.x;
    int lane = tid & 31, wid = tid >> 5;

    __shared__ int s_chunk_base;
    __shared__ int wsum[SCAN_BLOCK / 32];
    __shared__ int woff[SCAN_BLOCK / 32];

    // prefix of chunk sums before this block: sum g_bsum[0..b)
    {
        int v = 0;
        if (tid < NB_SCAN && tid < b) v = g_bsum[tid];
#pragma unroll
        for (int d = 16; d > 0; d >>= 1) v += __shfl_down_sync(0xffffffffu, v, d);
        if (lane == 0) wsum[wid] = v;
        __syncthreads();
        if (tid == 0) {
            int s = 0;
#pragma unroll
            for (int w = 0; w < SCAN_BLOCK / 32; w++) s += wsum[w];
            s_chunk_base = s;
        }
        __syncthreads();
    }

    int base = b * CHUNK + tid * SCAN_ITEMS;
    int v[SCAN_ITEMS];
    int run = 0;
#pragma unroll
    for (int i = 0; i < SCAN_ITEMS; i++) {
        int h = g_hist[base + i];
        v[i] = run;
        run += h;
    }
    int inc = run;
#pragma unroll
    for (int d = 1; d < 32; d <<= 1) {
        int t = __shfl_up_sync(0xffffffffu, inc, d);
        if (lane >= d) inc += t;
    }
    if (lane == 31) wsum[wid] = inc;
    __syncthreads();
    if (tid == 0) {
        int s = 0;
#pragma unroll
        for (int w = 0; w < SCAN_BLOCK / 32; w++) { woff[w] = s; s += wsum[w]; }
    }
    __syncthreads();
    int ex = inc - run + woff[wid] + s_chunk_base;
#pragma unroll
    for (int i = 0; i < SCAN_ITEMS; i++)
        g_off[base + i] = ex + v[i];
}

// K3: scatter points into Morton-sorted order
__global__ void k_scatter(const float* __restrict__ x) {
    int pt = blockIdx.x * blockDim.x + threadIdx.x;
    if (pt >= B_PTS) return;
    int c = g_cellid[pt];
    int pos = atomicAdd(&g_off[c], 1);
    float4 s;
    s.x = x[3 * pt + 0];
    s.y = x[3 * pt + 1];
    s.z = x[3 * pt + 2];
    s.w = __int_as_float(pt);
    g_sorted[pos] = s;
}

// ---------------------------------------------------------------------------
// K4: trilinear gather over Morton-sorted points.
// 64 threads per point (each owns one float4 of the 256-wide row);
// 1024-thread blocks = 16 spatially-clustered points sharing one L1.
__global__ __launch_bounds__(MAIN_BLOCK) void k_interp(
    const float* __restrict__ grid_value,
    const float* __restrict__ grid_feature,
    float* __restrict__ out,
    float* __restrict__ feat)
{
    int gid  = blockIdx.x * MAIN_BLOCK + threadIdx.x;
    int grp  = gid >> 6;
    int lane = gid & 63;
    if (grp >= B_PTS) return;

    float4 s = g_sorted[grp];
    int pt = __float_as_int(s.w);

    float rx = (s.x + 1.0f) * 32.0f;
    float ry = (s.y + 1.0f) * 32.0f;
    float rz = (s.z + 1.0f) * 32.0f;

    bool valid = (rx >= 0.0f) && (rx <= 64.0f) &&
                 (ry >= 0.0f) && (ry <= 64.0f) &&
                 (rz >= 0.0f) && (rz <= 64.0f);

    int ix = min(max((int)floorf(rx), 0), N_GRID - 1);
    int iy = min(max((int)floorf(ry), 0), N_GRID - 1);
    int iz = min(max((int)floorf(rz), 0), N_GRID - 1);

    float tx = rx - (float)ix;
    float ty = ry - (float)iy;
    float tz = rz - (float)iz;
    float ux = 1.0f - tx, uy = 1.0f - ty, uz = 1.0f - tz;

    float w[8];
    w[0] = ux * uy * uz;
    w[1] = ux * uy * tz;
    w[2] = ux * ty * uz;
    w[3] = ux * ty * tz;
    w[4] = tx * uy * uz;
    w[5] = tx * uy * tz;
    w[6] = tx * ty * uz;
    w[7] = tx * ty * tz;

    int base = (ix * N1 + iy) * N1 + iz;
    int off[8];
    off[0] = base;
    off[1] = base + 1;
    off[2] = base + N1;
    off[3] = base + N1 + 1;
    off[4] = base + N1 * N1;
    off[5] = base + N1 * N1 + 1;
    off[6] = base + N1 * N1 + N1;
    off[7] = base + N1 * N1 + N1 + 1;

    float4 acc = make_float4(0.f, 0.f, 0.f, 0.f);
#pragma unroll
    for (int c = 0; c < 8; c++) {
        const float4* row = reinterpret_cast<const float4*>(
            grid_feature + (size_t)off[c] * W_FEAT);
        float4 v = __ldg(row + lane);
        float wc = w[c];
        acc.x = fmaf(wc, v.x, acc.x);
        acc.y = fmaf(wc, v.y, acc.y);
        acc.z = fmaf(wc, v.z, acc.z);
        acc.w = fmaf(wc, v.w, acc.w);
    }

    if (!valid) acc = make_float4(0.f, 0.f, 0.f, 0.f);
    // Streaming store: write-once output must not evict feature rows from L2
    __stcs(reinterpret_cast<float4*>(feat + (size_t)pt * W_FEAT) + lane, acc);

    if (lane == 0) {
        float sv = 0.0f;
#pragma unroll
        for (int c = 0; c < 8; c++)
            sv = fmaf(w[c], __ldg(&grid_value[off[c]]), sv);
        __stcs(&out[pt], valid ? sv : 0.0f);
    }
}

// ---------------------------------------------------------------------------
extern "C" void kernel_launch(void* const* d_in, const int* in_sizes, int n_in,
                              void* d_out, int out_size)
{
    const float* x            = (const float*)d_in[0];
    const float* grid_value   = (const float*)d_in[1];
    const float* grid_feature = (const float*)d_in[2];
    float* out  = (float*)d_out;          // [B,1]
    float* feat = (float*)d_out + B_PTS;  // [B,256]

    k_zero_hist<<<NBINS / 1024, 1024>>>();
    k_cells<<<B_PTS / 256, 256>>>(x);
    k_reduce<<<NB_SCAN, SCAN_BLOCK>>>();
    k_scan_chunks<<<NB_SCAN, SCAN_BLOCK>>>();
    k_scatter<<<B_PTS / 256, 256>>>(x);

    k_interp<<<B_PTS * 64 / MAIN_BLOCK, MAIN_BLOCK>>>(grid_value, grid_feature, out, feat);
}

// round 7
// speedup vs baseline: 1.1148x; 1.1148x over previous
#include <cuda_runtime.h>

#define N_GRID 64
#define N1 65
#define B_PTS 262144
#define W_FEAT 256
#define NBINS 262144                       // 64^3 row-major bins (compact key)
#define SCAN_BLOCK 256
#define SCAN_ITEMS 8
#define CHUNK (SCAN_BLOCK * SCAN_ITEMS)    // 2048
#define NB_SCAN (NBINS / CHUNK)            // 128
#define MAIN_BLOCK 512

// Scratch (device globals: allocation-free per harness rules)
__device__ int    g_hist[NBINS];
__device__ int    g_off[NBINS];
__device__ int    g_bsum[NB_SCAN];
__device__ int    g_cellid[B_PTS];
__device__ float4 g_sorted[B_PTS];         // (px,py,pz, bitcast(pt))

// ---------------------------------------------------------------------------
// K0: zero histogram (every call, for graph-replay determinism)
__global__ void k_zero_hist() {
    int i = blockIdx.x * blockDim.x + threadIdx.x;
    g_hist[i] = 0;
}

// K1: row-major compact cell id per point + histogram
__global__ void k_cells(const float* __restrict__ x) {
    int pt = blockIdx.x * blockDim.x + threadIdx.x;
    if (pt >= B_PTS) return;
    float rx = (x[3 * pt + 0] + 1.0f) * 32.0f;
    float ry = (x[3 * pt + 1] + 1.0f) * 32.0f;
    float rz = (x[3 * pt + 2] + 1.0f) * 32.0f;
    int ix = min(max((int)floorf(rx), 0), N_GRID - 1);
    int iy = min(max((int)floorf(ry), 0), N_GRID - 1);
    int iz = min(max((int)floorf(rz), 0), N_GRID - 1);
    int cell = (ix << 12) | (iy << 6) | iz;   // same ordering as (ix*N1+iy)*N1+iz
    g_cellid[pt] = cell;
    atomicAdd(&g_hist[cell], 1);
}

// K2a: per-chunk reduction -> g_bsum[b]
__global__ void k_reduce() {
    int b = blockIdx.x, tid = threadIdx.x;
    int s = 0;
#pragma unroll
    for (int i = 0; i < SCAN_ITEMS; i++)
        s += g_hist[b * CHUNK + tid * SCAN_ITEMS + i];
#pragma unroll
    for (int d = 16; d > 0; d >>= 1) s += __shfl_down_sync(0xffffffffu, s, d);
    __shared__ int wsum[SCAN_BLOCK / 32];
    int lane = tid & 31, wid = tid >> 5;
    if (lane == 0) wsum[wid] = s;
    __syncthreads();
    if (wid == 0) {
        s = (lane < SCAN_BLOCK / 32) ? wsum[lane] : 0;
#pragma unroll
        for (int d = 16; d > 0; d >>= 1) s += __shfl_down_sync(0xffffffffu, s, d);
        if (lane == 0) g_bsum[b] = s;
    }
}

// K2b: per-chunk exclusive scan; each block derives its own prefix of g_bsum
// inline (128 entries fit in one warp-span reduce), avoiding a third launch.
__global__ void k_scan_chunks() {
    int b = blockIdx.x, tid = threadIdx.x;
    int lane = tid & 31, wid = tid >> 5;

    __shared__ int s_chunk_base;
    __shared__ int wsum[SCAN_BLOCK / 32];
    __shared__ int woff[SCAN_BLOCK / 32];

    // prefix of chunk sums before this block: sum g_bsum[0..b)
    {
        int v = 0;
        if (tid < NB_SCAN && tid < b) v = g_bsum[tid];
#pragma unroll
        for (int d = 16; d > 0; d >>= 1) v += __shfl_down_sync(0xffffffffu, v, d);
        if (lane == 0) wsum[wid] = v;
        __syncthreads();
        if (tid == 0) {
            int s = 0;
#pragma unroll
            for (int w = 0; w < SCAN_BLOCK / 32; w++) s += wsum[w];
            s_chunk_base = s;
        }
        __syncthreads();
    }

    int base = b * CHUNK + tid * SCAN_ITEMS;
    int v[SCAN_ITEMS];
    int run = 0;
#pragma unroll
    for (int i = 0; i < SCAN_ITEMS; i++) {
        int h = g_hist[base + i];
        v[i] = run;
        run += h;
    }
    int inc = run;
#pragma unroll
    for (int d = 1; d < 32; d <<= 1) {
        int t = __shfl_up_sync(0xffffffffu, inc, d);
        if (lane >= d) inc += t;
    }
    if (lane == 31) wsum[wid] = inc;
    __syncthreads();
    if (tid == 0) {
        int s = 0;
#pragma unroll
        for (int w = 0; w < SCAN_BLOCK / 32; w++) { woff[w] = s; s += wsum[w]; }
    }
    __syncthreads();
    int ex = inc - run + woff[wid] + s_chunk_base;
#pragma unroll
    for (int i = 0; i < SCAN_ITEMS; i++)
        g_off[base + i] = ex + v[i];
}

// K3: scatter points into cell-sorted order
__global__ void k_scatter(const float* __restrict__ x) {
    int pt = blockIdx.x * blockDim.x + threadIdx.x;
    if (pt >= B_PTS) return;
    int c = g_cellid[pt];
    int pos = atomicAdd(&g_off[c], 1);
    float4 s;
    s.x = x[3 * pt + 0];
    s.y = x[3 * pt + 1];
    s.z = x[3 * pt + 2];
    s.w = __int_as_float(pt);
    g_sorted[pos] = s;
}

// ---------------------------------------------------------------------------
// K4: trilinear gather over cell-sorted points (row-major order -> the 8
// corner-row streams advance near-sequentially through DRAM).
// 64 threads per point; each owns one float4 of the 256-wide feature row.
__global__ __launch_bounds__(MAIN_BLOCK) void k_interp(
    const float* __restrict__ grid_value,
    const float* __restrict__ grid_feature,
    float* __restrict__ out,
    float* __restrict__ feat)
{
    int gid  = blockIdx.x * MAIN_BLOCK + threadIdx.x;
    int grp  = gid >> 6;
    int lane = gid & 63;
    if (grp >= B_PTS) return;

    float4 s = g_sorted[grp];
    int pt = __float_as_int(s.w);

    float rx = (s.x + 1.0f) * 32.0f;
    float ry = (s.y + 1.0f) * 32.0f;
    float rz = (s.z + 1.0f) * 32.0f;

    bool valid = (rx >= 0.0f) && (rx <= 64.0f) &&
                 (ry >= 0.0f) && (ry <= 64.0f) &&
                 (rz >= 0.0f) && (rz <= 64.0f);

    int ix = min(max((int)floorf(rx), 0), N_GRID - 1);
    int iy = min(max((int)floorf(ry), 0), N_GRID - 1);
    int iz = min(max((int)floorf(rz), 0), N_GRID - 1);

    float tx = rx - (float)ix;
    float ty = ry - (float)iy;
    float tz = rz - (float)iz;
    float ux = 1.0f - tx, uy = 1.0f - ty, uz = 1.0f - tz;

    float w[8];
    w[0] = ux * uy * uz;
    w[1] = ux * uy * tz;
    w[2] = ux * ty * uz;
    w[3] = ux * ty * tz;
    w[4] = tx * uy * uz;
    w[5] = tx * uy * tz;
    w[6] = tx * ty * uz;
    w[7] = tx * ty * tz;

    int base = (ix * N1 + iy) * N1 + iz;
    int off[8];
    off[0] = base;
    off[1] = base + 1;
    off[2] = base + N1;
    off[3] = base + N1 + 1;
    off[4] = base + N1 * N1;
    off[5] = base + N1 * N1 + 1;
    off[6] = base + N1 * N1 + N1;
    off[7] = base + N1 * N1 + N1 + 1;

    float4 acc = make_float4(0.f, 0.f, 0.f, 0.f);
#pragma unroll
    for (int c = 0; c < 8; c++) {
        const float4* row = reinterpret_cast<const float4*>(
            grid_feature + (size_t)off[c] * W_FEAT);
        float4 v = __ldg(row + lane);
        float wc = w[c];
        acc.x = fmaf(wc, v.x, acc.x);
        acc.y = fmaf(wc, v.y, acc.y);
        acc.z = fmaf(wc, v.z, acc.z);
        acc.w = fmaf(wc, v.w, acc.w);
    }

    if (!valid) acc = make_float4(0.f, 0.f, 0.f, 0.f);
    // Streaming store: write-once output must not evict feature rows from L2
    __stcs(reinterpret_cast<float4*>(feat + (size_t)pt * W_FEAT) + lane, acc);

    if (lane == 0) {
        float sv = 0.0f;
#pragma unroll
        for (int c = 0; c < 8; c++)
            sv = fmaf(w[c], __ldg(&grid_value[off[c]]), sv);
        __stcs(&out[pt], valid ? sv : 0.0f);
    }
}

// ---------------------------------------------------------------------------
extern "C" void kernel_launch(void* const* d_in, const int* in_sizes, int n_in,
                              void* d_out, int out_size)
{
    const float* x            = (const float*)d_in[0];
    const float* grid_value   = (const float*)d_in[1];
    const float* grid_feature = (const float*)d_in[2];
    float* out  = (float*)d_out;          // [B,1]
    float* feat = (float*)d_out + B_PTS;  // [B,256]

    k_zero_hist<<<NBINS / 1024, 1024>>>();
    k_cells<<<B_PTS / 256, 256>>>(x);
    k_reduce<<<NB_SCAN, SCAN_BLOCK>>>();
    k_scan_chunks<<<NB_SCAN, SCAN_BLOCK>>>();
    k_scatter<<<B_PTS / 256, 256>>>(x);

    k_interp<<<B_PTS * 64 / MAIN_BLOCK, MAIN_BLOCK>>>(grid_value, grid_feature, out, feat);
}